// round 2
// baseline (speedup 1.0000x reference)
#include <cuda_runtime.h>

// ---------------- fixed problem capacities (dataset is fixed) ----------------
#define NMAX 100000
#define EMAX 3200000
#define HDIM 64
#define ODIM 32
#define FDIM 128

// ---------------- device scratch (no allocations allowed) ----------------
__device__ int   g_is32;                              // 1 if edge indices are int32
__device__ int   g_ecnt[NMAX];                        // in-degree (no self loop)
__device__ int   g_ptr[NMAX + 1];                     // CSR offsets
__device__ int   g_cursor[NMAX];                      // fill cursors
__device__ int   g_bsum[1024];                        // block sums for scan
__device__ float g_dinv[NMAX];                        // 1/sqrt(deg+1)
__device__ __align__(16) int   g_rows[EMAX];          // CSR adjacency: src per slot
__device__ __align__(16) float g_s1[NMAX * HDIM];     // dinv * (x @ W1)
__device__ __align__(16) float g_z1[NMAX * HDIM];     // relu layer-1 output
__device__ __align__(16) float g_s2[NMAX * ODIM];     // dinv * (z1 @ W2)
__device__ __align__(16) float g_z2[NMAX * ODIM];     // layer-2 output

// fetch edge value j from a buffer that is either int32[2E] or int64[2E]
__device__ __forceinline__ int edge_at(const void* p, long long j, int is32) {
    if (is32) return ((const int*)p)[j];
    return (int)((const long long*)p)[j];
}

// ---------------- dtype detection ----------------
__global__ void k_detect(const void* ei, int E) {
    // interpret as int64; if any of the first 256 values is out of [0, NMAX),
    // the underlying data must be int32 pairs.
    __shared__ int bad;
    if (threadIdx.x == 0) bad = 0;
    __syncthreads();
    int n = (2 * E < 256) ? 2 * E : 256;
    if (threadIdx.x < n) {
        long long v = ((const long long*)ei)[threadIdx.x];
        if (v < 0 || v >= NMAX) atomicOr(&bad, 1);
    }
    __syncthreads();
    if (threadIdx.x == 0) g_is32 = bad;
}

// ---------------- CSR build ----------------
__global__ void k_init(int N) {
    int i = blockIdx.x * blockDim.x + threadIdx.x;
    if (i < N) g_ecnt[i] = 0;
}

__global__ void k_count(const void* __restrict__ ei, int E) {
    int e = blockIdx.x * blockDim.x + threadIdx.x;
    if (e < E) {
        int c = edge_at(ei, (long long)E + e, g_is32);
        atomicAdd(&g_ecnt[c], 1);
    }
}

// block-local exclusive scan; writes partial to g_ptr, block total to g_bsum
__global__ void k_scanA(int N) {
    __shared__ int sh[1024];
    int t = threadIdx.x;
    int i = blockIdx.x * 1024 + t;
    int v = (i < N) ? g_ecnt[i] : 0;
    sh[t] = v;
    __syncthreads();
    for (int off = 1; off < 1024; off <<= 1) {
        int y = 0;
        if (t >= off) y = sh[t - off];
        __syncthreads();
        sh[t] += y;
        __syncthreads();
    }
    if (i < N) g_ptr[i] = sh[t] - v;     // exclusive within block
    if (t == 1023) g_bsum[blockIdx.x] = sh[1023];
}

__global__ void k_scanB(int NB) {
    __shared__ int sh[1024];
    int t = threadIdx.x;
    int v = (t < NB) ? g_bsum[t] : 0;
    sh[t] = v;
    __syncthreads();
    for (int off = 1; off < 1024; off <<= 1) {
        int y = 0;
        if (t >= off) y = sh[t - off];
        __syncthreads();
        sh[t] += y;
        __syncthreads();
    }
    if (t < NB) g_bsum[t] = sh[t] - v;   // exclusive
}

__global__ void k_scanC(int N, int E) {
    int i = blockIdx.x * 1024 + threadIdx.x;
    if (i < N) {
        int p = g_ptr[i] + g_bsum[blockIdx.x];
        g_ptr[i] = p;
        g_cursor[i] = p;
        g_dinv[i] = rsqrtf((float)(g_ecnt[i] + 1));   // +1 self loop
    }
    if (i == 0) g_ptr[N] = E;
}

__global__ void k_fill(const void* __restrict__ ei, int E) {
    int e = blockIdx.x * blockDim.x + threadIdx.x;
    if (e < E) {
        int is32 = g_is32;
        int r = edge_at(ei, e, is32);
        int c = edge_at(ei, (long long)E + e, is32);
        int pos = atomicAdd(&g_cursor[c], 1);
        g_rows[pos] = r;
    }
}

// ---------------- GEMM1: s1 = dinv * (x @ W1)   [N,128]x[128,64] ----------------
__global__ __launch_bounds__(256) void k_gemm1(const float* __restrict__ x,
                                               const float* __restrict__ W1, int N) {
    __shared__ float Ws[FDIM * HDIM];        // 32 KB
    __shared__ float xs[32 * FDIM];          // 16 KB
    int t = threadIdx.x;
    for (int i = t; i < FDIM * HDIM; i += 256) Ws[i] = W1[i];
    int node0 = blockIdx.x * 32;
    const float4* x4 = (const float4*)x;
    float4* xs4 = (float4*)xs;
    for (int i = t; i < 32 * (FDIM / 4); i += 256) {
        int n = i >> 5, kc = i & 31;
        int gn = node0 + n;
        xs4[i] = (gn < N) ? x4[gn * (FDIM / 4) + kc] : make_float4(0.f, 0.f, 0.f, 0.f);
    }
    __syncthreads();
    int node = t >> 3, og = t & 7;           // 32 nodes x 8 out-groups (8 outs each)
    float acc[8];
#pragma unroll
    for (int i = 0; i < 8; i++) acc[i] = 0.f;
    const float4* Ws4 = (const float4*)Ws;
    const float* xrow = &xs[node * FDIM];
#pragma unroll 4
    for (int k = 0; k < FDIM; k++) {
        float xk = xrow[k];
        float4 w0 = Ws4[k * 16 + og * 2];
        float4 w1 = Ws4[k * 16 + og * 2 + 1];
        acc[0] = fmaf(xk, w0.x, acc[0]);
        acc[1] = fmaf(xk, w0.y, acc[1]);
        acc[2] = fmaf(xk, w0.z, acc[2]);
        acc[3] = fmaf(xk, w0.w, acc[3]);
        acc[4] = fmaf(xk, w1.x, acc[4]);
        acc[5] = fmaf(xk, w1.y, acc[5]);
        acc[6] = fmaf(xk, w1.z, acc[6]);
        acc[7] = fmaf(xk, w1.w, acc[7]);
    }
    int gn = node0 + node;
    if (gn < N) {
        float d = g_dinv[gn];
        float4* s14 = (float4*)g_s1;
        s14[gn * 16 + og * 2]     = make_float4(d * acc[0], d * acc[1], d * acc[2], d * acc[3]);
        s14[gn * 16 + og * 2 + 1] = make_float4(d * acc[4], d * acc[5], d * acc[6], d * acc[7]);
    }
}

// ---------------- agg1 + finalize: z1 = relu(dinv*(sum + self) + b1) ----------------
__global__ __launch_bounds__(256) void k_agg1(const float* __restrict__ b1, int N) {
    int w = (blockIdx.x * blockDim.x + threadIdx.x) >> 5;
    int lane = threadIdx.x & 31;
    if (w >= N) return;
    int beg = g_ptr[w], end = g_ptr[w + 1];
    const float2* s1v = (const float2*)g_s1;
    float2 self = s1v[w * 32 + lane];
    float ax = self.x, ay = self.y;
    int i = beg;
    for (; i + 4 <= end; i += 4) {
        int r0 = g_rows[i], r1 = g_rows[i + 1], r2 = g_rows[i + 2], r3 = g_rows[i + 3];
        float2 v0 = s1v[r0 * 32 + lane];
        float2 v1 = s1v[r1 * 32 + lane];
        float2 v2 = s1v[r2 * 32 + lane];
        float2 v3 = s1v[r3 * 32 + lane];
        ax += (v0.x + v1.x) + (v2.x + v3.x);
        ay += (v0.y + v1.y) + (v2.y + v3.y);
    }
    for (; i < end; i++) {
        int r = g_rows[i];
        float2 v = s1v[r * 32 + lane];
        ax += v.x; ay += v.y;
    }
    float d = g_dinv[w];
    float2 bb = ((const float2*)b1)[lane];
    float zx = fmaxf(fmaf(d, ax, bb.x), 0.f);
    float zy = fmaxf(fmaf(d, ay, bb.y), 0.f);
    ((float2*)g_z1)[w * 32 + lane] = make_float2(zx, zy);
}

// ---------------- GEMM2: s2 = dinv * (z1 @ W2)   [N,64]x[64,32] ----------------
__global__ __launch_bounds__(256) void k_gemm2(const float* __restrict__ W2, int N) {
    __shared__ float Ws[HDIM * ODIM];        // 8 KB
    __shared__ float zs[32 * HDIM];          // 8 KB
    int t = threadIdx.x;
    for (int i = t; i < HDIM * ODIM; i += 256) Ws[i] = W2[i];
    int node0 = blockIdx.x * 32;
    const float4* z4 = (const float4*)g_z1;
    float4* zs4 = (float4*)zs;
    for (int i = t; i < 32 * (HDIM / 4); i += 256) {
        int n = i >> 4, kc = i & 15;
        int gn = node0 + n;
        zs4[i] = (gn < N) ? z4[gn * (HDIM / 4) + kc] : make_float4(0.f, 0.f, 0.f, 0.f);
    }
    __syncthreads();
    int node = t >> 3, og = t & 7;           // 32 nodes x 8 groups (4 outs each)
    float acc[4] = {0.f, 0.f, 0.f, 0.f};
    const float4* Ws4 = (const float4*)Ws;
    const float* zrow = &zs[node * HDIM];
#pragma unroll 4
    for (int k = 0; k < HDIM; k++) {
        float xk = zrow[k];
        float4 w = Ws4[k * 8 + og];
        acc[0] = fmaf(xk, w.x, acc[0]);
        acc[1] = fmaf(xk, w.y, acc[1]);
        acc[2] = fmaf(xk, w.z, acc[2]);
        acc[3] = fmaf(xk, w.w, acc[3]);
    }
    int gn = node0 + node;
    if (gn < N) {
        float d = g_dinv[gn];
        ((float4*)g_s2)[gn * 8 + og] =
            make_float4(d * acc[0], d * acc[1], d * acc[2], d * acc[3]);
    }
}

// ---------------- agg2 + finalize: z2 = dinv*(sum + self) + b2 ----------------
__global__ __launch_bounds__(256) void k_agg2(const float* __restrict__ b2, int N) {
    int w = (blockIdx.x * blockDim.x + threadIdx.x) >> 5;
    int lane = threadIdx.x & 31;
    if (w >= N) return;
    int beg = g_ptr[w], end = g_ptr[w + 1];
    float acc = g_s2[w * 32 + lane];
    int i = beg;
    for (; i + 4 <= end; i += 4) {
        int r0 = g_rows[i], r1 = g_rows[i + 1], r2 = g_rows[i + 2], r3 = g_rows[i + 3];
        float v0 = g_s2[r0 * 32 + lane];
        float v1 = g_s2[r1 * 32 + lane];
        float v2 = g_s2[r2 * 32 + lane];
        float v3 = g_s2[r3 * 32 + lane];
        acc += (v0 + v1) + (v2 + v3);
    }
    for (; i < end; i++) acc += g_s2[g_rows[i] * 32 + lane];
    g_z2[w * 32 + lane] = fmaf(g_dinv[w], acc, b2[lane]);
}

// ---------------- decode: out[p] = dot(z2[a], z2[b]) over 32 dims ----------------
__global__ __launch_bounds__(256) void k_decode(const void* __restrict__ eli,
                                                float* __restrict__ out, int EL) {
    int t = blockIdx.x * blockDim.x + threadIdx.x;
    int p = t >> 3;
    int j = t & 7;
    if (p >= EL) return;
    int is32 = g_is32;
    int a = edge_at(eli, p, is32);
    int b = edge_at(eli, (long long)EL + p, is32);
    float4 va = ((const float4*)g_z2)[a * 8 + j];
    float4 vb = ((const float4*)g_z2)[b * 8 + j];
    float s = va.x * vb.x + va.y * vb.y + va.z * vb.z + va.w * vb.w;
    s += __shfl_down_sync(0xffffffffu, s, 4, 8);
    s += __shfl_down_sync(0xffffffffu, s, 2, 8);
    s += __shfl_down_sync(0xffffffffu, s, 1, 8);
    if (j == 0) out[p] = s;
}

// ---------------- launch ----------------
extern "C" void kernel_launch(void* const* d_in, const int* in_sizes, int n_in,
                              void* d_out, int out_size) {
    const float* x   = (const float*)d_in[0];
    const float* W1  = (const float*)d_in[1];
    const float* b1  = (const float*)d_in[2];
    const float* W2  = (const float*)d_in[3];
    const float* b2  = (const float*)d_in[4];
    const void*  ei  = d_in[5];
    const void*  eli = d_in[6];

    int H  = in_sizes[2];                 // 64
    int F  = in_sizes[1] / H;             // 128
    int N  = in_sizes[0] / F;             // 100000
    int E  = in_sizes[5] / 2;             // 3200000
    int EL = in_sizes[6] / 2;             // 200000
    float* out = (float*)d_out;

    int NB1024 = (N + 1023) / 1024;

    // dtype detect + CSR build (reused for both layers)
    k_detect<<<1, 256>>>(ei, E);
    k_init<<<(N + 255) / 256, 256>>>(N);
    k_count<<<(E + 255) / 256, 256>>>(ei, E);
    k_scanA<<<NB1024, 1024>>>(N);
    k_scanB<<<1, 1024>>>(NB1024);
    k_scanC<<<NB1024, 1024>>>(N, E);
    k_fill<<<(E + 255) / 256, 256>>>(ei, E);

    // layer 1
    k_gemm1<<<(N + 31) / 32, 256>>>(x, W1, N);
    k_agg1<<<(N + 7) / 8, 256>>>(b1, N);

    // layer 2
    k_gemm2<<<(N + 31) / 32, 256>>>(W2, N);
    k_agg2<<<(N + 7) / 8, 256>>>(b2, N);

    // link decode
    k_decode<<<(EL * 8 + 255) / 256, 256>>>(eli, out, EL);
}

// round 3
// speedup vs baseline: 1.5720x; 1.5720x over previous
#include <cuda_runtime.h>
#include <cuda_fp16.h>

// ---------------- fixed problem capacities (dataset is fixed) ----------------
#define NMAX 100000
#define EMAX 3200000
#define HDIM 64
#define ODIM 32
#define FDIM 128
#define XSTR 65   // padded [k][n] stride: conflict-free for both stage-write and read

// ---------------- device scratch (no allocations allowed) ----------------
__device__ int   g_is32;                              // 1 if edge indices are int32
__device__ int   g_ecnt[NMAX];                        // in-degree (no self loop)
__device__ int   g_ptr[NMAX + 1];                     // CSR offsets
__device__ int   g_cursor[NMAX];                      // fill cursors
__device__ int   g_bsum[1024];                        // block sums for scan
__device__ float g_dinv[NMAX];                        // 1/sqrt(deg+1)
__device__ __align__(16) int     g_rows[EMAX];        // CSR adjacency: src per slot
__device__ __align__(16) __half2 g_s1h[NMAX * 32];    // fp16: dinv * (x @ W1), 64 vals/node
__device__ __align__(16) float   g_z1[NMAX * HDIM];   // relu layer-1 output (fp32)
__device__ __align__(16) float   g_s2[NMAX * ODIM];   // dinv * (z1 @ W2)
__device__ __align__(16) float   g_z2[NMAX * ODIM];   // layer-2 output

// fetch edge value j from a buffer that is either int32[2E] or int64[2E]
__device__ __forceinline__ int edge_at(const void* p, long long j, int is32) {
    if (is32) return ((const int*)p)[j];
    return (int)((const long long*)p)[j];
}

// ---------------- prep: dtype detect (block 0) + zero counters (all blocks) ----------------
__global__ void k_prep(const void* ei, int E, int N) {
    int i = blockIdx.x * blockDim.x + threadIdx.x;
    if (i < N) g_ecnt[i] = 0;
    if (blockIdx.x == 0) {
        __shared__ int bad;
        if (threadIdx.x == 0) bad = 0;
        __syncthreads();
        int n = (2 * E < 256) ? 2 * E : 256;
        if (threadIdx.x < n) {
            long long v = ((const long long*)ei)[threadIdx.x];
            if (v < 0 || v >= NMAX) atomicOr(&bad, 1);
        }
        __syncthreads();
        if (threadIdx.x == 0) g_is32 = bad;
    }
}

__global__ void k_count(const void* __restrict__ ei, int E) {
    int e = blockIdx.x * blockDim.x + threadIdx.x;
    if (e < E) {
        int c = edge_at(ei, (long long)E + e, g_is32);
        atomicAdd(&g_ecnt[c], 1);
    }
}

// block-local exclusive scan; partials to g_ptr, block totals to g_bsum
__global__ void k_scanA(int N) {
    __shared__ int sh[1024];
    int t = threadIdx.x;
    int i = blockIdx.x * 1024 + t;
    int v = (i < N) ? g_ecnt[i] : 0;
    sh[t] = v;
    __syncthreads();
    for (int off = 1; off < 1024; off <<= 1) {
        int y = 0;
        if (t >= off) y = sh[t - off];
        __syncthreads();
        sh[t] += y;
        __syncthreads();
    }
    if (i < N) g_ptr[i] = sh[t] - v;
    if (t == 1023) g_bsum[blockIdx.x] = sh[1023];
}

__global__ void k_scanB(int NB) {
    __shared__ int sh[1024];
    int t = threadIdx.x;
    int v = (t < NB) ? g_bsum[t] : 0;
    sh[t] = v;
    __syncthreads();
    for (int off = 1; off < 1024; off <<= 1) {
        int y = 0;
        if (t >= off) y = sh[t - off];
        __syncthreads();
        sh[t] += y;
        __syncthreads();
    }
    if (t < NB) g_bsum[t] = sh[t] - v;
}

__global__ void k_scanC(int N, int E) {
    int i = blockIdx.x * 1024 + threadIdx.x;
    if (i < N) {
        int p = g_ptr[i] + g_bsum[blockIdx.x];
        g_ptr[i] = p;
        g_cursor[i] = p;
        g_dinv[i] = rsqrtf((float)(g_ecnt[i] + 1));   // +1 self loop
    }
    if (i == 0) g_ptr[N] = E;
}

__global__ void k_fill(const void* __restrict__ ei, int E) {
    int e = blockIdx.x * blockDim.x + threadIdx.x;
    if (e < E) {
        int is32 = g_is32;
        int r = edge_at(ei, e, is32);
        int c = edge_at(ei, (long long)E + e, is32);
        int pos = atomicAdd(&g_cursor[c], 1);
        g_rows[pos] = r;
    }
}

// ---------------- GEMM1: s1h = fp16( dinv * (x @ W1) )   [N,128]x[128,64] ----------------
// 64 nodes/block, 256 threads: thread = (node n = t&63, out-group og = t>>6 -> 16 outs)
__global__ __launch_bounds__(256) void k_gemm1(const float* __restrict__ x,
                                               const float* __restrict__ W1, int N) {
    extern __shared__ float sm[];
    float* Ws = sm;                         // [128][64] row-major, 32KB
    float* xs = sm + FDIM * HDIM;           // [k][n] stride XSTR, 128*65*4 = 33.3KB
    int t = threadIdx.x;
    for (int i = t; i < FDIM * HDIM; i += 256) Ws[i] = W1[i];

    int node0 = blockIdx.x * 64;
    int lane = t & 31, wrp = t >> 5;        // 8 warps stage 8 nodes each
#pragma unroll
    for (int rep = 0; rep < 32; rep++) {
        int n = wrp * 8 + (rep >> 2);
        int k = (rep & 3) * 32 + lane;
        int gn = node0 + n;
        float v = (gn < N) ? x[(size_t)gn * FDIM + k] : 0.f;
        xs[k * XSTR + n] = v;               // bank = (k + n) % 32 within warp: conflict-free
    }
    __syncthreads();

    int n = t & 63;
    int og = t >> 6;                        // 0..3, outputs og*16 .. og*16+15
    float acc[16];
#pragma unroll
    for (int i = 0; i < 16; i++) acc[i] = 0.f;
    const float4* Ws4 = (const float4*)Ws;
#pragma unroll 4
    for (int k = 0; k < FDIM; k++) {
        float xv = xs[k * XSTR + n];
        float4 w0 = Ws4[k * 16 + og * 4 + 0];
        float4 w1 = Ws4[k * 16 + og * 4 + 1];
        float4 w2 = Ws4[k * 16 + og * 4 + 2];
        float4 w3 = Ws4[k * 16 + og * 4 + 3];
        acc[0]  = fmaf(xv, w0.x, acc[0]);  acc[1]  = fmaf(xv, w0.y, acc[1]);
        acc[2]  = fmaf(xv, w0.z, acc[2]);  acc[3]  = fmaf(xv, w0.w, acc[3]);
        acc[4]  = fmaf(xv, w1.x, acc[4]);  acc[5]  = fmaf(xv, w1.y, acc[5]);
        acc[6]  = fmaf(xv, w1.z, acc[6]);  acc[7]  = fmaf(xv, w1.w, acc[7]);
        acc[8]  = fmaf(xv, w2.x, acc[8]);  acc[9]  = fmaf(xv, w2.y, acc[9]);
        acc[10] = fmaf(xv, w2.z, acc[10]); acc[11] = fmaf(xv, w2.w, acc[11]);
        acc[12] = fmaf(xv, w3.x, acc[12]); acc[13] = fmaf(xv, w3.y, acc[13]);
        acc[14] = fmaf(xv, w3.z, acc[14]); acc[15] = fmaf(xv, w3.w, acc[15]);
    }
    int gn = node0 + n;
    if (gn < N) {
        float d = g_dinv[gn];
        unsigned int p[8];
#pragma unroll
        for (int j = 0; j < 8; j++) {
            __half2 h = __floats2half2_rn(d * acc[2 * j], d * acc[2 * j + 1]);
            p[j] = *(unsigned int*)&h;
        }
        uint4* dst = (uint4*)(g_s1h + (size_t)gn * 32 + og * 8);
        dst[0] = make_uint4(p[0], p[1], p[2], p[3]);
        dst[1] = make_uint4(p[4], p[5], p[6], p[7]);
    }
}

// ---------------- agg1: z1 = relu(dinv*(sum_nbrs s1h + self) + b1) ----------------
__global__ __launch_bounds__(256) void k_agg1(const float* __restrict__ b1, int N) {
    int w = (blockIdx.x * blockDim.x + threadIdx.x) >> 5;
    int lane = threadIdx.x & 31;
    if (w >= N) return;
    int beg = g_ptr[w], end = g_ptr[w + 1];
    float2 a = __half22float2(g_s1h[(size_t)w * 32 + lane]);   // self
    float ax = a.x, ay = a.y;
    int i = beg;
    for (; i + 8 <= end; i += 8) {
        int r0 = g_rows[i],     r1 = g_rows[i + 1], r2 = g_rows[i + 2], r3 = g_rows[i + 3];
        int r4 = g_rows[i + 4], r5 = g_rows[i + 5], r6 = g_rows[i + 6], r7 = g_rows[i + 7];
        float2 v0 = __half22float2(g_s1h[(size_t)r0 * 32 + lane]);
        float2 v1 = __half22float2(g_s1h[(size_t)r1 * 32 + lane]);
        float2 v2 = __half22float2(g_s1h[(size_t)r2 * 32 + lane]);
        float2 v3 = __half22float2(g_s1h[(size_t)r3 * 32 + lane]);
        float2 v4 = __half22float2(g_s1h[(size_t)r4 * 32 + lane]);
        float2 v5 = __half22float2(g_s1h[(size_t)r5 * 32 + lane]);
        float2 v6 = __half22float2(g_s1h[(size_t)r6 * 32 + lane]);
        float2 v7 = __half22float2(g_s1h[(size_t)r7 * 32 + lane]);
        ax += ((v0.x + v1.x) + (v2.x + v3.x)) + ((v4.x + v5.x) + (v6.x + v7.x));
        ay += ((v0.y + v1.y) + (v2.y + v3.y)) + ((v4.y + v5.y) + (v6.y + v7.y));
    }
    for (; i < end; i++) {
        float2 v = __half22float2(g_s1h[(size_t)g_rows[i] * 32 + lane]);
        ax += v.x; ay += v.y;
    }
    float d = g_dinv[w];
    float2 bb = ((const float2*)b1)[lane];
    float zx = fmaxf(fmaf(d, ax, bb.x), 0.f);
    float zy = fmaxf(fmaf(d, ay, bb.y), 0.f);
    ((float2*)g_z1)[(size_t)w * 32 + lane] = make_float2(zx, zy);
}

// ---------------- GEMM2: s2 = dinv * (z1 @ W2)   [N,64]x[64,32] ----------------
// 64 nodes/block, 256 threads: thread = (node n = t&63, og = t>>6 -> 8 outs)
__global__ __launch_bounds__(256) void k_gemm2(const float* __restrict__ W2, int N) {
    __shared__ float Ws[HDIM * ODIM];         // 8KB
    __shared__ float zs[HDIM * XSTR];         // [k][n] 64*65*4 = 16.6KB
    int t = threadIdx.x;
    for (int i = t; i < HDIM * ODIM; i += 256) Ws[i] = W2[i];

    int node0 = blockIdx.x * 64;
    int lane = t & 31, wrp = t >> 5;
#pragma unroll
    for (int rep = 0; rep < 16; rep++) {
        int n = wrp * 8 + (rep >> 1);
        int k = (rep & 1) * 32 + lane;
        int gn = node0 + n;
        float v = (gn < N) ? g_z1[(size_t)gn * HDIM + k] : 0.f;
        zs[k * XSTR + n] = v;
    }
    __syncthreads();

    int n = t & 63;
    int og = t >> 6;                          // 0..3, outputs og*8 .. og*8+7
    float acc[8];
#pragma unroll
    for (int i = 0; i < 8; i++) acc[i] = 0.f;
    const float4* Ws4 = (const float4*)Ws;
#pragma unroll 4
    for (int k = 0; k < HDIM; k++) {
        float xv = zs[k * XSTR + n];
        float4 w0 = Ws4[k * 8 + og * 2];
        float4 w1 = Ws4[k * 8 + og * 2 + 1];
        acc[0] = fmaf(xv, w0.x, acc[0]); acc[1] = fmaf(xv, w0.y, acc[1]);
        acc[2] = fmaf(xv, w0.z, acc[2]); acc[3] = fmaf(xv, w0.w, acc[3]);
        acc[4] = fmaf(xv, w1.x, acc[4]); acc[5] = fmaf(xv, w1.y, acc[5]);
        acc[6] = fmaf(xv, w1.z, acc[6]); acc[7] = fmaf(xv, w1.w, acc[7]);
    }
    int gn = node0 + n;
    if (gn < N) {
        float d = g_dinv[gn];
        float4* dst = (float4*)(g_s2 + (size_t)gn * ODIM + og * 8);
        dst[0] = make_float4(d * acc[0], d * acc[1], d * acc[2], d * acc[3]);
        dst[1] = make_float4(d * acc[4], d * acc[5], d * acc[6], d * acc[7]);
    }
}

// ---------------- agg2: z2 = dinv*(sum + self) + b2 ----------------
__global__ __launch_bounds__(256) void k_agg2(const float* __restrict__ b2, int N) {
    int w = (blockIdx.x * blockDim.x + threadIdx.x) >> 5;
    int lane = threadIdx.x & 31;
    if (w >= N) return;
    int beg = g_ptr[w], end = g_ptr[w + 1];
    float acc = g_s2[(size_t)w * 32 + lane];
    int i = beg;
    for (; i + 8 <= end; i += 8) {
        int r0 = g_rows[i],     r1 = g_rows[i + 1], r2 = g_rows[i + 2], r3 = g_rows[i + 3];
        int r4 = g_rows[i + 4], r5 = g_rows[i + 5], r6 = g_rows[i + 6], r7 = g_rows[i + 7];
        float v0 = g_s2[(size_t)r0 * 32 + lane];
        float v1 = g_s2[(size_t)r1 * 32 + lane];
        float v2 = g_s2[(size_t)r2 * 32 + lane];
        float v3 = g_s2[(size_t)r3 * 32 + lane];
        float v4 = g_s2[(size_t)r4 * 32 + lane];
        float v5 = g_s2[(size_t)r5 * 32 + lane];
        float v6 = g_s2[(size_t)r6 * 32 + lane];
        float v7 = g_s2[(size_t)r7 * 32 + lane];
        acc += ((v0 + v1) + (v2 + v3)) + ((v4 + v5) + (v6 + v7));
    }
    for (; i < end; i++) acc += g_s2[(size_t)g_rows[i] * 32 + lane];
    g_z2[(size_t)w * 32 + lane] = fmaf(g_dinv[w], acc, b2[lane]);
}

// ---------------- decode: out[p] = dot(z2[a], z2[b]) over 32 dims ----------------
__global__ __launch_bounds__(256) void k_decode(const void* __restrict__ eli,
                                                float* __restrict__ out, int EL) {
    int t = blockIdx.x * blockDim.x + threadIdx.x;
    int p = t >> 3;
    int j = t & 7;
    if (p >= EL) return;
    int is32 = g_is32;
    int a = edge_at(eli, p, is32);
    int b = edge_at(eli, (long long)EL + p, is32);
    float4 va = ((const float4*)g_z2)[a * 8 + j];
    float4 vb = ((const float4*)g_z2)[b * 8 + j];
    float s = va.x * vb.x + va.y * vb.y + va.z * vb.z + va.w * vb.w;
    s += __shfl_down_sync(0xffffffffu, s, 4, 8);
    s += __shfl_down_sync(0xffffffffu, s, 2, 8);
    s += __shfl_down_sync(0xffffffffu, s, 1, 8);
    if (j == 0) out[p] = s;
}

// ---------------- launch ----------------
extern "C" void kernel_launch(void* const* d_in, const int* in_sizes, int n_in,
                              void* d_out, int out_size) {
    const float* x   = (const float*)d_in[0];
    const float* W1  = (const float*)d_in[1];
    const float* b1  = (const float*)d_in[2];
    const float* W2  = (const float*)d_in[3];
    const float* b2  = (const float*)d_in[4];
    const void*  ei  = d_in[5];
    const void*  eli = d_in[6];

    int H  = in_sizes[2];                 // 64
    int F  = in_sizes[1] / H;             // 128
    int N  = in_sizes[0] / F;             // 100000
    int E  = in_sizes[5] / 2;             // 3200000
    int EL = in_sizes[6] / 2;             // 200000
    float* out = (float*)d_out;

    int NB1024 = (N + 1023) / 1024;
    int gemm1_smem = (FDIM * HDIM + FDIM * XSTR) * sizeof(float);   // ~66KB
    cudaFuncSetAttribute(k_gemm1, cudaFuncAttributeMaxDynamicSharedMemorySize, gemm1_smem);

    // CSR build (reused for both layers)
    k_prep<<<(N + 255) / 256, 256>>>(ei, E, N);
    k_count<<<(E + 511) / 512, 512>>>(ei, E);
    k_scanA<<<NB1024, 1024>>>(N);
    k_scanB<<<1, 1024>>>(NB1024);
    k_scanC<<<NB1024, 1024>>>(N, E);
    k_fill<<<(E + 511) / 512, 512>>>(ei, E);

    // layer 1
    k_gemm1<<<(N + 63) / 64, 256, gemm1_smem>>>(x, W1, N);
    k_agg1<<<(N + 7) / 8, 256>>>(b1, N);

    // layer 2
    k_gemm2<<<(N + 63) / 64, 256>>>(W2, N);
    k_agg2<<<(N + 7) / 8, 256>>>(b2, N);

    // link decode
    k_decode<<<(EL * 8 + 255) / 256, 256>>>(eli, out, EL);
}